// round 16
// baseline (speedup 1.0000x reference)
#include <cuda_runtime.h>
#include <cuda_fp16.h>

#define N_NODES 100000
#define N_EDGES 1200000
#define FDIM 64
#define KDIM 192                            // 3 * FDIM (concat t0|t1|p2)
#define NB_SCAN ((N_NODES + 1023) / 1024)   // 98
#define E_PAD (N_EDGES + 3 * N_NODES + 16)  // padded edge capacity

// smem layout (dynamic): fp16 weights [192][72], then act tile [64][200]
#define WS 72                                // weight row stride (halves)
#define AS 200                               // act row stride (halves)
#define SMEM_W_BYTES (KDIM * WS * 2)         // 27648
#define SMEM_ACT_OFF SMEM_W_BYTES
#define SMEM_TOTAL (SMEM_W_BYTES + 64 * AS * 2)  // 53248

// ---------------- scratch (device globals; no allocation allowed) -------------
__device__ int      g_is64;
__device__ int      g_degs[N_NODES];
__device__ int      g_degd[N_NODES];
__device__ int      g_rowptr[N_NODES + 1];
__device__ int      g_cursor[N_NODES];
__device__ int      g_bsum[NB_SCAN];
__device__ int4     g_edge4[E_PAD / 2];
__device__ __half   g_xh [N_NODES * FDIM];
__device__ __half   g_t1h[N_NODES * FDIM];
__device__ __half   g_p2h[N_NODES * FDIM];
__device__ __half   g_hAh[N_NODES * FDIM];
__device__ __half   g_hBh[N_NODES * FDIM];
__device__ float    g_Wp[3][KDIM * FDIM];   // transformed weights, [192][64] f32
__device__ unsigned g_bar_count;
__device__ unsigned g_bar_gen;

// ---------------- launch 1 ----------------------------------------------------
__global__ void init_kernel(const int* __restrict__ ei32) {
    int i = blockIdx.x * blockDim.x + threadIdx.x;
    if (i < N_NODES) { g_degs[i] = 0; g_degd[i] = 0; }
    if (i == 0) {
        int odd_zero = 1;
        for (int k = 0; k < 512; k++)
            if (ei32[2 * k + 1] != 0) { odd_zero = 0; break; }
        g_is64 = odd_zero;
        g_bar_count = 0;
        g_bar_gen = 0;
    }
}

__device__ __forceinline__ void load_edge(const void* ei, int e, int& s, int& d) {
    if (g_is64) {
        const long long* p = (const long long*)ei;
        s = (int)p[e]; d = (int)p[N_EDGES + e];
    } else {
        const int* p = (const int*)ei;
        s = p[e]; d = p[N_EDGES + e];
    }
    if ((unsigned)s >= N_NODES || (unsigned)d >= N_NODES) { s = 0; d = 0; }
}

// ---------------- launch 2 ----------------------------------------------------
__global__ void count_kernel(const void* __restrict__ ei) {
    int e = blockIdx.x * blockDim.x + threadIdx.x;
    if (e >= N_EDGES) return;
    int s, d;
    load_edge(ei, e, s, d);
    atomicAdd(&g_degs[s], 1);
    atomicAdd(&g_degd[d], 1);
}

// ---------------- launch 3: per-block scan of PADDED in-degrees ---------------
__global__ __launch_bounds__(1024) void scan1_kernel() {
    __shared__ int s[1024];
    int tid = threadIdx.x;
    int i = blockIdx.x * 1024 + tid;
    int v = (i < N_NODES) ? ((g_degd[i] + 3) & ~3) : 0;
    s[tid] = v;
    __syncthreads();
    for (int off = 1; off < 1024; off <<= 1) {
        int t = (tid >= off) ? s[tid - off] : 0;
        __syncthreads();
        s[tid] += t;
        __syncthreads();
    }
    int incl = s[tid];
    if (i < N_NODES) g_rowptr[i] = incl - v;
    if (tid == 1023) g_bsum[blockIdx.x] = incl;
}

// ---------------- grid-wide software barrier ----------------------------------
__device__ __forceinline__ void grid_barrier(int nblocks) {
    __syncthreads();
    if (threadIdx.x == 0) {
        __threadfence();
        unsigned gen = *(volatile unsigned*)&g_bar_gen;
        unsigned t = atomicAdd(&g_bar_count, 1u);
        if (t == (unsigned)nblocks - 1u) {
            g_bar_count = 0u;
            __threadfence();
            atomicAdd(&g_bar_gen, 1u);
        } else {
            while (*(volatile unsigned*)&g_bar_gen == gen) __nanosleep(64);
        }
        __threadfence();
    }
    __syncthreads();
}

// ---------------- pull phase (unchanged) ---------------------------------------
__device__ void pull_phase(const __half* __restrict__ in,
                           __half* __restrict__ out,
                           int gtid, int gstride) {
    for (int t = gtid; t < N_NODES * 8; t += gstride) {
        int node = t >> 3;
        int lane = t & 7;
        int e   = __ldg(&g_rowptr[node]);
        int end = __ldg(&g_rowptr[node + 1]);
        float acc[8];
#pragma unroll
        for (int j = 0; j < 8; j++) acc[j] = 0.f;

        if (e < end) {
            int4 qa = __ldg(&g_edge4[(e >> 1)]);
            int4 qb = __ldg(&g_edge4[(e >> 1) + 1]);
            while (true) {
                int4 na = __ldg(&g_edge4[(e >> 1) + 2]);
                int4 nb = __ldg(&g_edge4[(e >> 1) + 3]);
                uint4 v0 = __ldg((const uint4*)(in + qa.x * FDIM + lane * 8));
                uint4 v1 = __ldg((const uint4*)(in + qa.z * FDIM + lane * 8));
                uint4 v2 = __ldg((const uint4*)(in + qb.x * FDIM + lane * 8));
                uint4 v3 = __ldg((const uint4*)(in + qb.z * FDIM + lane * 8));
                float n0 = __int_as_float(qa.y), n1 = __int_as_float(qa.w);
                float n2 = __int_as_float(qb.y), n3 = __int_as_float(qb.w);
                const __half2* h0 = (const __half2*)&v0;
                const __half2* h1 = (const __half2*)&v1;
                const __half2* h2 = (const __half2*)&v2;
                const __half2* h3 = (const __half2*)&v3;
#pragma unroll
                for (int p = 0; p < 4; p++) {
                    float2 f0 = __half22float2(h0[p]);
                    float2 f1 = __half22float2(h1[p]);
                    float2 f2 = __half22float2(h2[p]);
                    float2 f3 = __half22float2(h3[p]);
                    acc[2*p]   = fmaf(n0, f0.x, acc[2*p]);
                    acc[2*p+1] = fmaf(n0, f0.y, acc[2*p+1]);
                    acc[2*p]   = fmaf(n1, f1.x, acc[2*p]);
                    acc[2*p+1] = fmaf(n1, f1.y, acc[2*p+1]);
                    acc[2*p]   = fmaf(n2, f2.x, acc[2*p]);
                    acc[2*p+1] = fmaf(n2, f2.y, acc[2*p+1]);
                    acc[2*p]   = fmaf(n3, f3.x, acc[2*p]);
                    acc[2*p+1] = fmaf(n3, f3.y, acc[2*p+1]);
                }
                e += 4;
                if (e >= end) break;
                qa = na; qb = nb;
            }
        }
        uint4 pk;
        __half2 ph0 = __floats2half2_rn(acc[0], acc[1]);
        __half2 ph1 = __floats2half2_rn(acc[2], acc[3]);
        __half2 ph2 = __floats2half2_rn(acc[4], acc[5]);
        __half2 ph3 = __floats2half2_rn(acc[6], acc[7]);
        pk.x = *(unsigned int*)&ph0; pk.y = *(unsigned int*)&ph1;
        pk.z = *(unsigned int*)&ph2; pk.w = *(unsigned int*)&ph3;
        *(uint4*)(out + node * FDIM + lane * 8) = pk;
    }
}

// ---------------- tensor-core GEMM phase --------------------------------------
__device__ __forceinline__ unsigned s2u(const void* p) {
    return (unsigned)__cvta_generic_to_shared(p);
}

__device__ void gemm_phase(const __half* __restrict__ t0h,
                           const __half* __restrict__ t1h,
                           const __half* __restrict__ p2h,
                           const float* __restrict__ Wp,
                           const float* __restrict__ bias,
                           const __half* __restrict__ skiph,
                           float* __restrict__ out32,
                           __half* __restrict__ outh,
                           char* smem, int nblocks) {
    __half* sWh  = (__half*)smem;                    // [192][WS]
    __half* sAct = (__half*)(smem + SMEM_ACT_OFF);   // [64][AS]

    for (int i = threadIdx.x; i < KDIM * FDIM / 2; i += 512) {
        int idx = i * 2;
        int row = idx >> 6, col = idx & 63;
        float2 w = *(const float2*)(Wp + idx);
        *(__half2*)(sWh + row * WS + col) = __floats2half2_rn(w.x, w.y);
    }
    __syncthreads();

    int tid  = threadIdx.x;
    int lane = tid & 31;
    int w    = tid >> 5;          // 0..15
    int mrow  = (w >> 2) * 16;
    int nbase = (w & 3) * 16;
    int g  = lane >> 2;
    int tg = lane & 3;

    unsigned aAddr0 = s2u(sAct + (mrow + (lane & 15)) * AS + ((lane >> 4) << 3));
    unsigned bAddr0 = s2u(sWh + (lane & 15) * WS + nbase + ((lane >> 4) << 3));

    const int ntiles = (N_NODES + 63) / 64;
    for (int tile = blockIdx.x; tile < ntiles; tile += nblocks) {
        int tb = tile * 64;

        for (int i = tid; i < 64 * 24; i += 512) {
            int row = i / 24, c = i % 24;
            int arr = c >> 3, off = (c & 7) * 8;
            int r = tb + row;
            uint4 v = make_uint4(0u, 0u, 0u, 0u);
            if (r < N_NODES) {
                const __half* src = (arr == 0) ? t0h : (arr == 1) ? t1h : p2h;
                v = __ldg((const uint4*)(src + r * FDIM + off));
            }
            *(uint4*)(sAct + row * AS + arr * 64 + off) = v;
        }
        __syncthreads();

        float d0[4] = {0.f, 0.f, 0.f, 0.f};
        float d1[4] = {0.f, 0.f, 0.f, 0.f};
#pragma unroll
        for (int ks = 0; ks < KDIM / 16; ks++) {
            unsigned a0, a1, a2, a3, b0, b1, b2, b3;
            asm volatile(
                "ldmatrix.sync.aligned.m8n8.x4.shared.b16 {%0,%1,%2,%3}, [%4];"
                : "=r"(a0), "=r"(a1), "=r"(a2), "=r"(a3)
                : "r"(aAddr0 + ks * 32));
            asm volatile(
                "ldmatrix.sync.aligned.m8n8.x4.trans.shared.b16 {%0,%1,%2,%3}, [%4];"
                : "=r"(b0), "=r"(b1), "=r"(b2), "=r"(b3)
                : "r"(bAddr0 + ks * (16 * WS * 2)));
            asm volatile(
                "mma.sync.aligned.m16n8k16.row.col.f32.f16.f16.f32 "
                "{%0,%1,%2,%3}, {%4,%5,%6,%7}, {%8,%9}, {%0,%1,%2,%3};"
                : "+f"(d0[0]), "+f"(d0[1]), "+f"(d0[2]), "+f"(d0[3])
                : "r"(a0), "r"(a1), "r"(a2), "r"(a3), "r"(b0), "r"(b1));
            asm volatile(
                "mma.sync.aligned.m16n8k16.row.col.f32.f16.f16.f32 "
                "{%0,%1,%2,%3}, {%4,%5,%6,%7}, {%8,%9}, {%0,%1,%2,%3};"
                : "+f"(d1[0]), "+f"(d1[1]), "+f"(d1[2]), "+f"(d1[3])
                : "r"(a0), "r"(a1), "r"(a2), "r"(a3), "r"(b2), "r"(b3));
        }

#pragma unroll
        for (int j = 0; j < 2; j++) {
            float* d = j ? d1 : d0;
            int col = nbase + j * 8 + tg * 2;
            float2 bi = __ldg((const float2*)(bias + col));
#pragma unroll
            for (int i = 0; i < 2; i++) {
                int r = tb + mrow + g + i * 8;
                if (r >= N_NODES) continue;
                float v0 = d[2 * i] + bi.x;
                float v1 = d[2 * i + 1] + bi.y;
                if (skiph) {
                    unsigned sk = __ldg((const unsigned*)(skiph + r * FDIM + col));
                    float2 sf = __half22float2(*(__half2*)&sk);
                    v0 += sf.x; v1 += sf.y;
                }
                v0 = fmaxf(v0, 0.f);
                v1 = fmaxf(v1, 0.f);
                if (out32)
                    *(float2*)(out32 + r * FDIM + col) = make_float2(v0, v1);
                if (outh) {
                    __half2 hh = __floats2half2_rn(v0, v1);
                    *(unsigned*)(outh + r * FDIM + col) = *(unsigned*)&hh;
                }
            }
        }
        __syncthreads();
    }
}

// ---------------- launch 4: persistent fused prep+compute ---------------------
__global__ __launch_bounds__(512, 3) void fused_kernel(
    const float* __restrict__ x, const void* __restrict__ ei,
    const float* __restrict__ W, const float* __restrict__ b,
    float* __restrict__ out, int nblocks) {
    extern __shared__ char smem[];
    int tid = threadIdx.x;
    int gtid = blockIdx.x * 512 + tid;
    int gstride = nblocks * 512;

    // ---- scan2 (block 0 only; scratch overlaid on smem) ----
    if (blockIdx.x == 0) {
        int* sh = (int*)smem;
        int v = 0;
        if (tid < 128) {
            v = (tid < NB_SCAN) ? g_bsum[tid] : 0;
            sh[tid] = v;
        }
        __syncthreads();
        for (int off = 1; off < 128; off <<= 1) {
            int t2 = 0;
            if (tid < 128 && tid >= off) t2 = sh[tid - off];
            __syncthreads();
            if (tid < 128) sh[tid] += t2;
            __syncthreads();
        }
        if (tid < NB_SCAN) {
            g_bsum[tid] = sh[tid] - v;
            if (tid == NB_SCAN - 1) g_rowptr[N_NODES] = sh[tid];
        }
    }
    grid_barrier(nblocks);

    // ---- scan3 ----
    for (int i = gtid; i < N_NODES; i += gstride) {
        int v = g_rowptr[i] + g_bsum[i >> 10];
        g_rowptr[i] = v;
        g_cursor[i] = v;
    }
    grid_barrier(nblocks);

    // ---- fill CSR + padding + weight transform + x->fp16 ----
    int2* edges = (int2*)g_edge4;
    for (int e = gtid; e < N_EDGES; e += gstride) {
        int s, d;
        load_edge(ei, e, s, d);
        int pos = atomicAdd(&g_cursor[d], 1);
        int pd = g_degs[s] * g_degs[d];
        float nv = (pd > 0) ? -rsqrtf((float)pd) : 0.0f;
        edges[pos] = make_int2(s, __float_as_int(nv));
    }
    for (int i = gtid; i < N_NODES; i += gstride) {
        int p0 = g_rowptr[i] + g_degd[i];
        int p1 = g_rowptr[i + 1];
        for (int p = p0; p < p1; p++) edges[p] = make_int2(0, 0);
    }
    for (int i = gtid; i < 3 * 3 * 4096; i += gstride) {
        int layer = i / 12288, rem = i % 12288;
        int t = rem / 4096, idx = rem % 4096;
        const float* Wl = W + layer * 12288;
        float v;
        if (t == 0)      v = Wl[idx] - Wl[2 * 4096 + idx];
        else if (t == 1) v = Wl[4096 + idx];
        else             v = 2.0f * Wl[2 * 4096 + idx];
        g_Wp[layer][t * 4096 + idx] = v;
    }
    for (int i = gtid; i < N_NODES * FDIM / 4; i += gstride) {
        float4 v = __ldg((const float4*)x + i);
        __half2 h0 = __floats2half2_rn(v.x, v.y);
        __half2 h1 = __floats2half2_rn(v.z, v.w);
        uint2 pk;
        pk.x = *(unsigned int*)&h0;
        pk.y = *(unsigned int*)&h1;
        ((uint2*)g_xh)[i] = pk;
    }
    grid_barrier(nblocks);

    // ---- layer 0 ----
    pull_phase(g_xh, g_t1h, gtid, gstride);
    grid_barrier(nblocks);
    pull_phase(g_t1h, g_p2h, gtid, gstride);
    grid_barrier(nblocks);
    gemm_phase(g_xh, g_t1h, g_p2h, g_Wp[0], b, nullptr,
               nullptr, g_hAh, smem, nblocks);
    grid_barrier(nblocks);
    // ---- layer 1 ----
    pull_phase(g_hAh, g_t1h, gtid, gstride);
    grid_barrier(nblocks);
    pull_phase(g_t1h, g_p2h, gtid, gstride);
    grid_barrier(nblocks);
    gemm_phase(g_hAh, g_t1h, g_p2h, g_Wp[1], b + FDIM, g_hAh,
               nullptr, g_hBh, smem, nblocks);
    grid_barrier(nblocks);
    // ---- layer 2 ----
    pull_phase(g_hBh, g_t1h, gtid, gstride);
    grid_barrier(nblocks);
    pull_phase(g_t1h, g_p2h, gtid, gstride);
    grid_barrier(nblocks);
    gemm_phase(g_hBh, g_t1h, g_p2h, g_Wp[2], b + 2 * FDIM, g_hBh,
               out, nullptr, smem, nblocks);
}

// ---------------- launch orchestration ---------------------------------------
static inline int cdiv(long long a, long long b) { return (int)((a + b - 1) / b); }

extern "C" void kernel_launch(void* const* d_in, const int* in_sizes, int n_in,
                              void* d_out, int out_size) {
    const float* x  = (const float*)d_in[0];
    const void*  ei = d_in[1];
    const float* W  = (const float*)d_in[2];
    const float* b  = (const float*)d_in[3];
    float*       out = (float*)d_out;

    init_kernel<<<cdiv(N_NODES, 256), 256>>>((const int*)ei);
    count_kernel<<<cdiv(N_EDGES, 256), 256>>>(ei);
    scan1_kernel<<<NB_SCAN, 1024>>>();

    cudaFuncSetAttribute(fused_kernel,
                         cudaFuncAttributeMaxDynamicSharedMemorySize,
                         SMEM_TOTAL);
    int dev = 0, nsm = 148, nb_per_sm = 0;
    cudaGetDevice(&dev);
    cudaDeviceGetAttribute(&nsm, cudaDevAttrMultiProcessorCount, dev);
    cudaOccupancyMaxActiveBlocksPerMultiprocessor(&nb_per_sm, fused_kernel,
                                                  512, SMEM_TOTAL);
    if (nb_per_sm < 1) nb_per_sm = 1;
    int nblocks = nsm * nb_per_sm;
    fused_kernel<<<nblocks, 512, SMEM_TOTAL>>>(x, ei, W, b, out, nblocks);
}